// round 1
// baseline (speedup 1.0000x reference)
#include <cuda_runtime.h>
#include <math.h>

#define Bb    2
#define Nn    1024
#define DIMM  1024
#define HEADS 16
#define HD    64
#define Mtot  (Bb * Nn)      // 2048
#define E3    (3 * DIMM)     // 3072

// ---------------- scratch (device globals; no allocation allowed) ----------
__device__ float g_Qr[Bb * HEADS * Nn * HD];
__device__ float g_Qi[Bb * HEADS * Nn * HD];
__device__ float g_Kr[Bb * HEADS * Nn * HD];
__device__ float g_Ki[Bb * HEADS * Nn * HD];
__device__ float g_Vr[Bb * HEADS * Nn * HD];
__device__ float g_Vi[Bb * HEADS * Nn * HD];
__device__ float g_AOr[Bb * Nn * DIMM];
__device__ float g_AOi[Bb * Nn * DIMM];

// ---------------- complex GEMM 1: qkv = x @ Wqkv^T + b, fused rotary -------
// C[m,e] = sum_k X[m,k] * W[e,k]   (complex). BM=BN=64, BK=16, 256 threads,
// 4x4 register micro-tile per thread.
#define BM 64
#define BN 64
#define BK 16

__global__ void __launch_bounds__(256, 2) qkv_gemm_kernel(
    const float* __restrict__ xr, const float* __restrict__ xi,
    const float* __restrict__ wr, const float* __restrict__ wi,
    const float* __restrict__ br, const float* __restrict__ bi,
    const float* __restrict__ fr, const float* __restrict__ fi)
{
    __shared__ float As_r[BK][BM], As_i[BK][BM];
    __shared__ float Bs_r[BK][BN], Bs_i[BK][BN];

    const int tid = threadIdx.x;
    const int tx  = tid & 15;
    const int ty  = tid >> 4;
    const int e0  = blockIdx.x * BN;
    const int m0  = blockIdx.y * BM;

    const int loadRow = tid & 63;        // 0..63
    const int loadK4  = (tid >> 6) * 4;  // 0,4,8,12

    float cr[4][4] = {}, ci[4][4] = {};

    for (int k0 = 0; k0 < DIMM; k0 += BK) {
        float4 a4r = *(const float4*)&xr[(size_t)(m0 + loadRow) * DIMM + k0 + loadK4];
        float4 a4i = *(const float4*)&xi[(size_t)(m0 + loadRow) * DIMM + k0 + loadK4];
        float4 b4r = *(const float4*)&wr[(size_t)(e0 + loadRow) * DIMM + k0 + loadK4];
        float4 b4i = *(const float4*)&wi[(size_t)(e0 + loadRow) * DIMM + k0 + loadK4];
        As_r[loadK4 + 0][loadRow] = a4r.x; As_r[loadK4 + 1][loadRow] = a4r.y;
        As_r[loadK4 + 2][loadRow] = a4r.z; As_r[loadK4 + 3][loadRow] = a4r.w;
        As_i[loadK4 + 0][loadRow] = a4i.x; As_i[loadK4 + 1][loadRow] = a4i.y;
        As_i[loadK4 + 2][loadRow] = a4i.z; As_i[loadK4 + 3][loadRow] = a4i.w;
        Bs_r[loadK4 + 0][loadRow] = b4r.x; Bs_r[loadK4 + 1][loadRow] = b4r.y;
        Bs_r[loadK4 + 2][loadRow] = b4r.z; Bs_r[loadK4 + 3][loadRow] = b4r.w;
        Bs_i[loadK4 + 0][loadRow] = b4i.x; Bs_i[loadK4 + 1][loadRow] = b4i.y;
        Bs_i[loadK4 + 2][loadRow] = b4i.z; Bs_i[loadK4 + 3][loadRow] = b4i.w;
        __syncthreads();

        #pragma unroll
        for (int kk = 0; kk < BK; kk++) {
            float4 ar4 = *(float4*)&As_r[kk][ty * 4];
            float4 ai4 = *(float4*)&As_i[kk][ty * 4];
            float4 br4 = *(float4*)&Bs_r[kk][tx * 4];
            float4 bi4 = *(float4*)&Bs_i[kk][tx * 4];
            float ar[4] = {ar4.x, ar4.y, ar4.z, ar4.w};
            float ai[4] = {ai4.x, ai4.y, ai4.z, ai4.w};
            float brr[4] = {br4.x, br4.y, br4.z, br4.w};
            float bii[4] = {bi4.x, bi4.y, bi4.z, bi4.w};
            #pragma unroll
            for (int i = 0; i < 4; i++)
                #pragma unroll
                for (int j = 0; j < 4; j++) {
                    cr[i][j] += ar[i] * brr[j] - ai[i] * bii[j];
                    ci[i][j] += ar[i] * bii[j] + ai[i] * brr[j];
                }
        }
        __syncthreads();
    }

    // epilogue: decode (h, d, which), bias, rotary for q/k, scatter
    #pragma unroll
    for (int i = 0; i < 4; i++) {
        #pragma unroll
        for (int j = 0; j < 4; j++) {
            const int m = m0 + ty * 4 + i;
            const int e = e0 + tx * 4 + j;
            float vr = cr[i][j] + br[e];
            float vi = ci[i][j] + bi[e];
            const int b = m >> 10;           // m / Nn
            const int n = m & 1023;          // m % Nn
            const int h = e / (HD * 3);
            const int rem = e % (HD * 3);
            const int d = rem / 3;
            const int which = rem % 3;
            const int idx = ((b * HEADS + h) * Nn + n) * HD + d;
            if (which == 2) {
                g_Vr[idx] = vr; g_Vi[idx] = vi;
            } else {
                const float frv = fr[n * HD + d];
                const float fiv = fi[n * HD + d];
                const float rr = vr * frv - vi * fiv;
                const float ii = vr * fiv + vi * frv;
                if (which == 0) { g_Qr[idx] = rr; g_Qi[idx] = ii; }
                else            { g_Kr[idx] = rr; g_Ki[idx] = ii; }
            }
        }
    }
}

// ---------------- fused attention (flash-style, 64-query tile) -------------
#define TP 65   // padded tile pitch
#define ATTN_SMEM ((7 * 64 * TP + 3 * 64) * (int)sizeof(float))

__global__ void __launch_bounds__(256, 1) attn_kernel()
{
    extern __shared__ float sm[];
    float* qs_r = sm;
    float* qs_i = qs_r + 64 * TP;
    float* ks_r = qs_i + 64 * TP;
    float* ks_i = ks_r + 64 * TP;
    float* vs_r = ks_i + 64 * TP;
    float* vs_i = vs_r + 64 * TP;
    float* Ps   = vs_i + 64 * TP;
    float* mrow = Ps + 64 * TP;
    float* lrow = mrow + 64;
    float* arow = lrow + 64;

    const int tid = threadIdx.x;
    const int tx  = tid & 15;
    const int ty  = tid >> 4;
    const int bh  = blockIdx.y;
    const int q0  = blockIdx.x * 64;

    const float* Qr = g_Qr + (size_t)bh * Nn * HD;
    const float* Qi = g_Qi + (size_t)bh * Nn * HD;
    const float* Kr = g_Kr + (size_t)bh * Nn * HD;
    const float* Ki = g_Ki + (size_t)bh * Nn * HD;
    const float* Vr = g_Vr + (size_t)bh * Nn * HD;
    const float* Vi = g_Vi + (size_t)bh * Nn * HD;

    // load Q tile
    for (int idx = tid; idx < 64 * 64; idx += 256) {
        const int r = idx >> 6, c = idx & 63;
        qs_r[r * TP + c] = Qr[(q0 + r) * HD + c];
        qs_i[r * TP + c] = Qi[(q0 + r) * HD + c];
    }
    if (tid < 64) { mrow[tid] = -1e30f; lrow[tid] = 0.0f; }

    float o_r[4][4] = {}, o_i[4][4] = {};
    __syncthreads();

    for (int kt = 0; kt < Nn / 64; kt++) {
        const int k0 = kt * 64;
        for (int idx = tid; idx < 64 * 64; idx += 256) {
            const int r = idx >> 6, c = idx & 63;
            ks_r[r * TP + c] = Kr[(k0 + r) * HD + c];
            ks_i[r * TP + c] = Ki[(k0 + r) * HD + c];
            vs_r[r * TP + c] = Vr[(k0 + r) * HD + c];
            vs_i[r * TP + c] = Vi[(k0 + r) * HD + c];
        }
        __syncthreads();

        // S = q . conj(k)
        float sr[4][4] = {}, si[4][4] = {};
        #pragma unroll 8
        for (int d = 0; d < 64; d++) {
            float qr_[4], qi_[4], kr_[4], ki_[4];
            #pragma unroll
            for (int i = 0; i < 4; i++) {
                qr_[i] = qs_r[(ty * 4 + i) * TP + d];
                qi_[i] = qs_i[(ty * 4 + i) * TP + d];
            }
            #pragma unroll
            for (int j = 0; j < 4; j++) {
                kr_[j] = ks_r[(tx * 4 + j) * TP + d];
                ki_[j] = ks_i[(tx * 4 + j) * TP + d];
            }
            #pragma unroll
            for (int i = 0; i < 4; i++)
                #pragma unroll
                for (int j = 0; j < 4; j++) {
                    sr[i][j] += qr_[i] * kr_[j] + qi_[i] * ki_[j];
                    si[i][j] += qi_[i] * kr_[j] - qr_[i] * ki_[j];
                }
        }

        // scaled abs + row max
        float sc[4][4];
        float rmax[4] = {-1e30f, -1e30f, -1e30f, -1e30f};
        #pragma unroll
        for (int i = 0; i < 4; i++)
            #pragma unroll
            for (int j = 0; j < 4; j++) {
                const float v = 0.125f * sqrtf(sr[i][j] * sr[i][j] + si[i][j] * si[i][j]);
                sc[i][j] = v;
                rmax[i] = fmaxf(rmax[i], v);
            }
        #pragma unroll
        for (int off = 1; off < 16; off <<= 1)
            #pragma unroll
            for (int i = 0; i < 4; i++)
                rmax[i] = fmaxf(rmax[i], __shfl_xor_sync(0xffffffffu, rmax[i], off));

        if (tx == 0) {
            #pragma unroll
            for (int i = 0; i < 4; i++) {
                const int r = ty * 4 + i;
                const float mo = mrow[r];
                const float mn = fmaxf(mo, rmax[i]);
                arow[r] = __expf(mo - mn);
                mrow[r] = mn;
            }
        }
        __syncthreads();

        // P = exp(S - m), write to smem, row sums, rescale O
        float rsum[4] = {0.f, 0.f, 0.f, 0.f};
        #pragma unroll
        for (int i = 0; i < 4; i++) {
            const float mn = mrow[ty * 4 + i];
            #pragma unroll
            for (int j = 0; j < 4; j++) {
                const float p = __expf(sc[i][j] - mn);
                Ps[(ty * 4 + i) * TP + tx * 4 + j] = p;
                rsum[i] += p;
            }
        }
        #pragma unroll
        for (int off = 1; off < 16; off <<= 1)
            #pragma unroll
            for (int i = 0; i < 4; i++)
                rsum[i] += __shfl_xor_sync(0xffffffffu, rsum[i], off);
        if (tx == 0) {
            #pragma unroll
            for (int i = 0; i < 4; i++) {
                const int r = ty * 4 + i;
                lrow[r] = lrow[r] * arow[r] + rsum[i];
            }
        }
        #pragma unroll
        for (int i = 0; i < 4; i++) {
            const float a = arow[ty * 4 + i];
            #pragma unroll
            for (int j = 0; j < 4; j++) { o_r[i][j] *= a; o_i[i][j] *= a; }
        }
        __syncthreads();

        // O += P @ V
        #pragma unroll 4
        for (int jj = 0; jj < 64; jj++) {
            float p[4], vrr[4], vii[4];
            #pragma unroll
            for (int i = 0; i < 4; i++) p[i] = Ps[(ty * 4 + i) * TP + jj];
            #pragma unroll
            for (int j = 0; j < 4; j++) {
                vrr[j] = vs_r[jj * TP + tx * 4 + j];
                vii[j] = vs_i[jj * TP + tx * 4 + j];
            }
            #pragma unroll
            for (int i = 0; i < 4; i++)
                #pragma unroll
                for (int j = 0; j < 4; j++) {
                    o_r[i][j] += p[i] * vrr[j];
                    o_i[i][j] += p[i] * vii[j];
                }
        }
        __syncthreads();
    }

    // normalize + write to [b, n, (h d)]
    const int b = bh / HEADS, h = bh % HEADS;
    #pragma unroll
    for (int i = 0; i < 4; i++) {
        const float inv = 1.0f / lrow[ty * 4 + i];
        const int n = q0 + ty * 4 + i;
        #pragma unroll
        for (int j = 0; j < 4; j++) {
            const int d = tx * 4 + j;
            const int idx = (b * Nn + n) * DIMM + h * HD + d;
            g_AOr[idx] = o_r[i][j] * inv;
            g_AOi[idx] = o_i[i][j] * inv;
        }
    }
}

// ---------------- complex GEMM 2: out = AO @ Wout^T + bout -----------------
__global__ void __launch_bounds__(256, 2) out_gemm_kernel(
    const float* __restrict__ wr, const float* __restrict__ wi,
    const float* __restrict__ br, const float* __restrict__ bi,
    float* __restrict__ out)
{
    __shared__ float As_r[BK][BM], As_i[BK][BM];
    __shared__ float Bs_r[BK][BN], Bs_i[BK][BN];

    const int tid = threadIdx.x;
    const int tx  = tid & 15;
    const int ty  = tid >> 4;
    const int e0  = blockIdx.x * BN;
    const int m0  = blockIdx.y * BM;

    const int loadRow = tid & 63;
    const int loadK4  = (tid >> 6) * 4;

    float cr[4][4] = {}, ci[4][4] = {};

    for (int k0 = 0; k0 < DIMM; k0 += BK) {
        float4 a4r = *(const float4*)&g_AOr[(size_t)(m0 + loadRow) * DIMM + k0 + loadK4];
        float4 a4i = *(const float4*)&g_AOi[(size_t)(m0 + loadRow) * DIMM + k0 + loadK4];
        float4 b4r = *(const float4*)&wr[(size_t)(e0 + loadRow) * DIMM + k0 + loadK4];
        float4 b4i = *(const float4*)&wi[(size_t)(e0 + loadRow) * DIMM + k0 + loadK4];
        As_r[loadK4 + 0][loadRow] = a4r.x; As_r[loadK4 + 1][loadRow] = a4r.y;
        As_r[loadK4 + 2][loadRow] = a4r.z; As_r[loadK4 + 3][loadRow] = a4r.w;
        As_i[loadK4 + 0][loadRow] = a4i.x; As_i[loadK4 + 1][loadRow] = a4i.y;
        As_i[loadK4 + 2][loadRow] = a4i.z; As_i[loadK4 + 3][loadRow] = a4i.w;
        Bs_r[loadK4 + 0][loadRow] = b4r.x; Bs_r[loadK4 + 1][loadRow] = b4r.y;
        Bs_r[loadK4 + 2][loadRow] = b4r.z; Bs_r[loadK4 + 3][loadRow] = b4r.w;
        Bs_i[loadK4 + 0][loadRow] = b4i.x; Bs_i[loadK4 + 1][loadRow] = b4i.y;
        Bs_i[loadK4 + 2][loadRow] = b4i.z; Bs_i[loadK4 + 3][loadRow] = b4i.w;
        __syncthreads();

        #pragma unroll
        for (int kk = 0; kk < BK; kk++) {
            float4 ar4 = *(float4*)&As_r[kk][ty * 4];
            float4 ai4 = *(float4*)&As_i[kk][ty * 4];
            float4 br4 = *(float4*)&Bs_r[kk][tx * 4];
            float4 bi4 = *(float4*)&Bs_i[kk][tx * 4];
            float ar[4] = {ar4.x, ar4.y, ar4.z, ar4.w};
            float ai[4] = {ai4.x, ai4.y, ai4.z, ai4.w};
            float brr[4] = {br4.x, br4.y, br4.z, br4.w};
            float bii[4] = {bi4.x, bi4.y, bi4.z, bi4.w};
            #pragma unroll
            for (int i = 0; i < 4; i++)
                #pragma unroll
                for (int j = 0; j < 4; j++) {
                    cr[i][j] += ar[i] * brr[j] - ai[i] * bii[j];
                    ci[i][j] += ar[i] * bii[j] + ai[i] * brr[j];
                }
        }
        __syncthreads();
    }

    #pragma unroll
    for (int i = 0; i < 4; i++)
        #pragma unroll
        for (int j = 0; j < 4; j++) {
            const int m = m0 + ty * 4 + i;
            const int e = e0 + tx * 4 + j;
            out[(size_t)m * DIMM + e] = cr[i][j] + br[e];
            out[(size_t)Mtot * DIMM + (size_t)m * DIMM + e] = ci[i][j] + bi[e];
        }
}

// ---------------- launch ----------------------------------------------------
extern "C" void kernel_launch(void* const* d_in, const int* in_sizes, int n_in,
                              void* d_out, int out_size)
{
    const float* xr  = (const float*)d_in[0];
    const float* xi  = (const float*)d_in[1];
    const float* fr  = (const float*)d_in[2];
    const float* fi  = (const float*)d_in[3];
    const float* wqr = (const float*)d_in[4];
    const float* wqi = (const float*)d_in[5];
    const float* bqr = (const float*)d_in[6];
    const float* bqi = (const float*)d_in[7];
    const float* wor = (const float*)d_in[8];
    const float* woi = (const float*)d_in[9];
    const float* bor = (const float*)d_in[10];
    const float* boi = (const float*)d_in[11];
    float* out = (float*)d_out;

    cudaFuncSetAttribute(attn_kernel,
                         cudaFuncAttributeMaxDynamicSharedMemorySize, ATTN_SMEM);

    qkv_gemm_kernel<<<dim3(E3 / BN, Mtot / BM), 256>>>(xr, xi, wqr, wqi, bqr, bqi, fr, fi);
    attn_kernel<<<dim3(Nn / 64, Bb * HEADS), 256, ATTN_SMEM>>>();
    out_gemm_kernel<<<dim3(DIMM / BN, Mtot / BM), 256>>>(wor, woi, bor, boi, out);
}

// round 3
// speedup vs baseline: 1.7538x; 1.7538x over previous
#include <cuda_runtime.h>
#include <cuda_bf16.h>
#include <stdint.h>
#include <math.h>

#define Bb    2
#define Nn    1024
#define DIMM  1024
#define HEADS 16
#define HD    64
#define Mtot  (Bb * Nn)      // 2048
#define E3    (3 * DIMM)     // 3072

// ---------------- fp32 scratch ----------------------------------------------
__device__ float g_Qr[Bb * HEADS * Nn * HD];
__device__ float g_Qi[Bb * HEADS * Nn * HD];
__device__ float g_Kr[Bb * HEADS * Nn * HD];
__device__ float g_Ki[Bb * HEADS * Nn * HD];
__device__ float g_Vr[Bb * HEADS * Nn * HD];
__device__ float g_Vi[Bb * HEADS * Nn * HD];
__device__ float g_AOr[Bb * Nn * DIMM];
__device__ float g_AOi[Bb * Nn * DIMM];

// ---------------- bf16 hi/lo split scratch -----------------------------------
__device__ __nv_bfloat16 g_Xr_h[Mtot * DIMM], g_Xr_l[Mtot * DIMM];
__device__ __nv_bfloat16 g_Xi_h[Mtot * DIMM], g_Xi_l[Mtot * DIMM];
__device__ __nv_bfloat16 g_Wqr_h[E3 * DIMM],  g_Wqr_l[E3 * DIMM];
__device__ __nv_bfloat16 g_Wqi_h[E3 * DIMM],  g_Wqi_l[E3 * DIMM];
__device__ __nv_bfloat16 g_Wor_h[DIMM * DIMM], g_Wor_l[DIMM * DIMM];
__device__ __nv_bfloat16 g_Woi_h[DIMM * DIMM], g_Woi_l[DIMM * DIMM];
__device__ __nv_bfloat16 g_Ar_h[Mtot * DIMM], g_Ar_l[Mtot * DIMM];
__device__ __nv_bfloat16 g_Ai_h[Mtot * DIMM], g_Ai_l[Mtot * DIMM];

// ---------------- helpers ----------------------------------------------------
__device__ __forceinline__ uint32_t smem_u32(const void* p) {
    uint32_t a;
    asm("{ .reg .u64 t; cvta.to.shared.u64 t, %1; cvt.u32.u64 %0, t; }"
        : "=r"(a) : "l"(p));
    return a;
}

#define CP16(dst, src) \
    asm volatile("cp.async.cg.shared.global [%0], [%1], 16;" \
                 :: "r"((uint32_t)(dst)), "l"(src) : "memory")
#define CP_COMMIT() asm volatile("cp.async.commit_group;" ::: "memory")
#define CP_WAIT(n)  asm volatile("cp.async.wait_group %0;" :: "n"(n) : "memory")

__device__ __forceinline__ void ldm_x4(uint32_t* r, uint32_t addr) {
    asm volatile("ldmatrix.sync.aligned.m8n8.x4.shared.b16 {%0,%1,%2,%3}, [%4];"
        : "=r"(r[0]), "=r"(r[1]), "=r"(r[2]), "=r"(r[3]) : "r"(addr));
}

__device__ __forceinline__ void mma16816(float* c, const uint32_t* a, const uint32_t* b) {
    asm volatile("mma.sync.aligned.m16n8k16.row.col.f32.bf16.bf16.f32 "
        "{%0,%1,%2,%3}, {%4,%5,%6,%7}, {%8,%9}, {%0,%1,%2,%3};"
        : "+f"(c[0]), "+f"(c[1]), "+f"(c[2]), "+f"(c[3])
        : "r"(a[0]), "r"(a[1]), "r"(a[2]), "r"(a[3]), "r"(b[0]), "r"(b[1]));
}

// ---------------- bf16 split conversion -------------------------------------
__global__ void __launch_bounds__(256) split_kernel(const float* __restrict__ src,
                                                    int which, int n)
{
    int i = (blockIdx.x * 256 + threadIdx.x) * 4;
    if (i >= n) return;
    __nv_bfloat16 *hi, *lo;
    switch (which) {
        case 0: hi = g_Xr_h;  lo = g_Xr_l;  break;
        case 1: hi = g_Xi_h;  lo = g_Xi_l;  break;
        case 2: hi = g_Wqr_h; lo = g_Wqr_l; break;
        case 3: hi = g_Wqi_h; lo = g_Wqi_l; break;
        case 4: hi = g_Wor_h; lo = g_Wor_l; break;
        case 5: hi = g_Woi_h; lo = g_Woi_l; break;
        case 6: hi = g_Ar_h;  lo = g_Ar_l;  src = g_AOr; break;
        default: hi = g_Ai_h; lo = g_Ai_l;  src = g_AOi; break;
    }
    float4 x = *(const float4*)(src + i);
    float xs[4] = {x.x, x.y, x.z, x.w};
    #pragma unroll
    for (int k = 0; k < 4; k++) {
        __nv_bfloat16 h = __float2bfloat16(xs[k]);
        float rem = xs[k] - __bfloat162float(h);
        hi[i + k] = h;
        lo[i + k] = __float2bfloat16(rem);
    }
}

// ---------------- mma.sync complex GEMM core ---------------------------------
// Block 128(m) x 64(n), 8 warps as 4(m) x 2(n), warp tile 32x32.
// K-chunk 32, double-buffered smem. Rows padded to pitch 40 bf16 (80 B):
// conflict-free ldmatrix.
// Stage layout (bytes): A[v] at v*10240 (128 rows x 80B), B[v] at 40960+v*5120.
#define STG 61440
#define GEMM_SMEM (2 * STG)
#define NCHUNK (DIMM / 32)

__device__ __forceinline__ void stage_load(uint32_t sA,
    const __nv_bfloat16* const* Av, const __nv_bfloat16* const* Bv,
    int m0, int e0, int k0, int tid)
{
    #pragma unroll
    for (int v = 0; v < 4; v++) {
        const __nv_bfloat16* srcA = Av[v] + (size_t)m0 * DIMM + k0;
        uint32_t dstA = sA + v * 10240u;
        #pragma unroll
        for (int t = 0; t < 2; t++) {
            int idx = tid + t * 256;
            int r = idx >> 2, c = idx & 3;
            CP16(dstA + r * 80 + c * 16, srcA + (size_t)r * DIMM + c * 8);
        }
        const __nv_bfloat16* srcB = Bv[v] + (size_t)e0 * DIMM + k0;
        uint32_t dstB = sA + 40960u + v * 5120u;
        {
            int r = tid >> 2, c = tid & 3;
            CP16(dstB + r * 80 + c * 16, srcB + (size_t)r * DIMM + c * 8);
        }
    }
}

__device__ __forceinline__ void gemm_compute(uint32_t ss, int lane, int wm, int wn,
    float accR[2][4][4], float accI[2][4][4])
{
    const uint32_t aRow = (uint32_t)(lane & 15);
    const uint32_t aSel = (uint32_t)(lane >> 4);
    const uint32_t nl   = (uint32_t)((lane & 7) + ((lane >> 4) << 3));
    const uint32_t ksel = (uint32_t)((lane >> 3) & 1);

    #pragma unroll
    for (int ks = 0; ks < 2; ks++) {
        uint32_t Af[4][2][4];   // [variant][mfrag][reg]
        #pragma unroll
        for (int v = 0; v < 4; v++)
            #pragma unroll
            for (int mf = 0; mf < 2; mf++) {
                uint32_t addr = ss + v * 10240u
                    + (wm * 32 + mf * 16 + aRow) * 80u + aSel * 16u + ks * 32u;
                ldm_x4(Af[v][mf], addr);
            }
        uint32_t nAih[2][4], nAil[2][4];
        #pragma unroll
        for (int mf = 0; mf < 2; mf++)
            #pragma unroll
            for (int q = 0; q < 4; q++) {
                nAih[mf][q] = Af[2][mf][q] ^ 0x80008000u;
                nAil[mf][q] = Af[3][mf][q] ^ 0x80008000u;
            }
        #pragma unroll
        for (int h = 0; h < 2; h++) {
            uint32_t Bf[4][4];
            #pragma unroll
            for (int v = 0; v < 4; v++) {
                uint32_t addr = ss + 40960u + v * 5120u
                    + (wn * 32 + h * 16 + nl) * 80u + ksel * 16u + ks * 32u;
                ldm_x4(Bf[v], addr);
            }
            #pragma unroll
            for (int mf = 0; mf < 2; mf++)
                #pragma unroll
                for (int sub = 0; sub < 2; sub++) {
                    const int nf = h * 2 + sub;
                    const uint32_t* Brh = &Bf[0][sub * 2];
                    const uint32_t* Brl = &Bf[1][sub * 2];
                    const uint32_t* Bih = &Bf[2][sub * 2];
                    const uint32_t* Bil = &Bf[3][sub * 2];
                    float* cr = accR[mf][nf];
                    float* ci = accI[mf][nf];
                    // real: ArBr - AiBi (3-term splits, lo*lo dropped)
                    mma16816(cr, Af[0][mf], Brh);
                    mma16816(cr, Af[0][mf], Brl);
                    mma16816(cr, Af[1][mf], Brh);
                    mma16816(cr, nAih[mf],  Bih);
                    mma16816(cr, nAih[mf],  Bil);
                    mma16816(cr, nAil[mf],  Bih);
                    // imag: ArBi + AiBr
                    mma16816(ci, Af[0][mf], Bih);
                    mma16816(ci, Af[0][mf], Bil);
                    mma16816(ci, Af[1][mf], Bih);
                    mma16816(ci, Af[2][mf], Brh);
                    mma16816(ci, Af[2][mf], Brl);
                    mma16816(ci, Af[3][mf], Brh);
                }
        }
    }
}

// ---------------- qkv GEMM: fused bias + rotary + scatter --------------------
__global__ void __launch_bounds__(256, 1) qkv_mma_kernel(
    const float* __restrict__ br, const float* __restrict__ bi,
    const float* __restrict__ fr, const float* __restrict__ fi)
{
    extern __shared__ char smrw[];
    const uint32_t sb = smem_u32(smrw);
    const int tid = threadIdx.x, lane = tid & 31, wid = tid >> 5;
    const int wm = wid >> 1, wn = wid & 1;
    const int e0 = blockIdx.x * 64, m0 = blockIdx.y * 128;

    const __nv_bfloat16* Av[4] = {g_Xr_h, g_Xr_l, g_Xi_h, g_Xi_l};
    const __nv_bfloat16* Bv[4] = {g_Wqr_h, g_Wqr_l, g_Wqi_h, g_Wqi_l};

    float accR[2][4][4] = {}, accI[2][4][4] = {};

    stage_load(sb, Av, Bv, m0, e0, 0, tid);
    CP_COMMIT();

    #pragma unroll 1
    for (int c = 0; c < NCHUNK; c++) {
        const int s = c & 1;
        if (c + 1 < NCHUNK) {
            stage_load(sb + (s ^ 1) * STG, Av, Bv, m0, e0, (c + 1) * 32, tid);
            CP_COMMIT();
            CP_WAIT(1);
        } else {
            CP_WAIT(0);
        }
        __syncthreads();
        gemm_compute(sb + s * STG, lane, wm, wn, accR, accI);
        __syncthreads();
    }

    #pragma unroll
    for (int mf = 0; mf < 2; mf++)
        #pragma unroll
        for (int nf = 0; nf < 4; nf++)
            #pragma unroll
            for (int rp = 0; rp < 2; rp++)
                #pragma unroll
                for (int cp = 0; cp < 2; cp++) {
                    const int m = m0 + wm * 32 + mf * 16 + (lane >> 2) + rp * 8;
                    const int e = e0 + wn * 32 + nf * 8 + (lane & 3) * 2 + cp;
                    const float vr = accR[mf][nf][rp * 2 + cp] + br[e];
                    const float vi = accI[mf][nf][rp * 2 + cp] + bi[e];
                    const int b = m >> 10;
                    const int n = m & 1023;
                    const int h = e / (HD * 3);
                    const int rem = e % (HD * 3);
                    const int d = rem / 3;
                    const int which = rem % 3;
                    const int idx = ((b * HEADS + h) * Nn + n) * HD + d;
                    if (which == 2) {
                        g_Vr[idx] = vr; g_Vi[idx] = vi;
                    } else {
                        const float frv = fr[n * HD + d];
                        const float fiv = fi[n * HD + d];
                        const float rr = vr * frv - vi * fiv;
                        const float ii = vr * fiv + vi * frv;
                        if (which == 0) { g_Qr[idx] = rr; g_Qi[idx] = ii; }
                        else            { g_Kr[idx] = rr; g_Ki[idx] = ii; }
                    }
                }
}

// ---------------- output GEMM ------------------------------------------------
__global__ void __launch_bounds__(256, 1) out_mma_kernel(
    const float* __restrict__ br, const float* __restrict__ bi,
    float* __restrict__ out)
{
    extern __shared__ char smrw[];
    const uint32_t sb = smem_u32(smrw);
    const int tid = threadIdx.x, lane = tid & 31, wid = tid >> 5;
    const int wm = wid >> 1, wn = wid & 1;
    const int e0 = blockIdx.x * 64, m0 = blockIdx.y * 128;

    const __nv_bfloat16* Av[4] = {g_Ar_h, g_Ar_l, g_Ai_h, g_Ai_l};
    const __nv_bfloat16* Bv[4] = {g_Wor_h, g_Wor_l, g_Woi_h, g_Woi_l};

    float accR[2][4][4] = {}, accI[2][4][4] = {};

    stage_load(sb, Av, Bv, m0, e0, 0, tid);
    CP_COMMIT();

    #pragma unroll 1
    for (int c = 0; c < NCHUNK; c++) {
        const int s = c & 1;
        if (c + 1 < NCHUNK) {
            stage_load(sb + (s ^ 1) * STG, Av, Bv, m0, e0, (c + 1) * 32, tid);
            CP_COMMIT();
            CP_WAIT(1);
        } else {
            CP_WAIT(0);
        }
        __syncthreads();
        gemm_compute(sb + s * STG, lane, wm, wn, accR, accI);
        __syncthreads();
    }

    #pragma unroll
    for (int mf = 0; mf < 2; mf++)
        #pragma unroll
        for (int nf = 0; nf < 4; nf++)
            #pragma unroll
            for (int rp = 0; rp < 2; rp++)
                #pragma unroll
                for (int cp = 0; cp < 2; cp++) {
                    const int m = m0 + wm * 32 + mf * 16 + (lane >> 2) + rp * 8;
                    const int e = e0 + wn * 32 + nf * 8 + (lane & 3) * 2 + cp;
                    out[(size_t)m * DIMM + e] = accR[mf][nf][rp * 2 + cp] + br[e];
                    out[(size_t)Mtot * DIMM + (size_t)m * DIMM + e] =
                        accI[mf][nf][rp * 2 + cp] + bi[e];
                }
}

// ---------------- fused attention (unchanged, known correct) -----------------
#define TP 65
#define ATTN_SMEM ((7 * 64 * TP + 3 * 64) * (int)sizeof(float))

__global__ void __launch_bounds__(256, 1) attn_kernel()
{
    extern __shared__ float sm[];
    float* qs_r = sm;
    float* qs_i = qs_r + 64 * TP;
    float* ks_r = qs_i + 64 * TP;
    float* ks_i = ks_r + 64 * TP;
    float* vs_r = ks_i + 64 * TP;
    float* vs_i = vs_r + 64 * TP;
    float* Ps   = vs_i + 64 * TP;
    float* mrow = Ps + 64 * TP;
    float* lrow = mrow + 64;
    float* arow = lrow + 64;

    const int tid = threadIdx.x;
    const int tx  = tid & 15;
    const int ty  = tid >> 4;
    const int bh  = blockIdx.y;
    const int q0  = blockIdx.x * 64;

    const float* Qr = g_Qr + (size_t)bh * Nn * HD;
    const float* Qi = g_Qi + (size_t)bh * Nn * HD;
    const float* Kr = g_Kr + (size_t)bh * Nn * HD;
    const float* Ki = g_Ki + (size_t)bh * Nn * HD;
    const float* Vr = g_Vr + (size_t)bh * Nn * HD;
    const float* Vi = g_Vi + (size_t)bh * Nn * HD;

    for (int idx = tid; idx < 64 * 64; idx += 256) {
        const int r = idx >> 6, c = idx & 63;
        qs_r[r * TP + c] = Qr[(q0 + r) * HD + c];
        qs_i[r * TP + c] = Qi[(q0 + r) * HD + c];
    }
    if (tid < 64) { mrow[tid] = -1e30f; lrow[tid] = 0.0f; }

    float o_r[4][4] = {}, o_i[4][4] = {};
    __syncthreads();

    for (int kt = 0; kt < Nn / 64; kt++) {
        const int k0 = kt * 64;
        for (int idx = tid; idx < 64 * 64; idx += 256) {
            const int r = idx >> 6, c = idx & 63;
            ks_r[r * TP + c] = Kr[(k0 + r) * HD + c];
            ks_i[r * TP + c] = Ki[(k0 + r) * HD + c];
            vs_r[r * TP + c] = Vr[(k0 + r) * HD + c];
            vs_i[r * TP + c] = Vi[(k0 + r) * HD + c];
        }
        __syncthreads();

        float sr[4][4] = {}, si[4][4] = {};
        #pragma unroll 8
        for (int d = 0; d < 64; d++) {
            float qr_[4], qi_[4], kr_[4], ki_[4];
            #pragma unroll
            for (int i = 0; i < 4; i++) {
                qr_[i] = qs_r[(ty * 4 + i) * TP + d];
                qi_[i] = qs_i[(ty * 4 + i) * TP + d];
            }
            #pragma unroll
            for (int j = 0; j < 4; j++) {
                kr_[j] = ks_r[(tx * 4 + j) * TP + d];
                ki_[j] = ks_i[(tx * 4 + j) * TP + d];
            }
            #pragma unroll
            for (int i = 0; i < 4; i++)
                #pragma unroll
                for (int j = 0; j < 4; j++) {
                    sr[i][j] += qr_[i] * kr_[j] + qi_[i] * ki_[j];
                    si[i][j] += qi_[i] * kr_[j] - qr_[i] * ki_[j];
                }
        }

        float sc[4][4];
        float rmax[4] = {-1e30f, -1e30f, -1e30f, -1e30f};
        #pragma unroll
        for (int i = 0; i < 4; i++)
            #pragma unroll
            for (int j = 0; j < 4; j++) {
                const float v = 0.125f * sqrtf(sr[i][j] * sr[i][j] + si[i][j] * si[i][j]);
                sc[i][j] = v;
                rmax[i] = fmaxf(rmax[i], v);
            }
        #pragma unroll
        for (int off = 1; off < 16; off <<= 1)
            #pragma unroll
            for (int i = 0; i < 4; i++)
                rmax[i] = fmaxf(rmax[i], __shfl_xor_sync(0xffffffffu, rmax[i], off));

        if (tx == 0) {
            #pragma unroll
            for (int i = 0; i < 4; i++) {
                const int r = ty * 4 + i;
                const float mo = mrow[r];
                const float mn = fmaxf(mo, rmax[i]);
                arow[r] = __expf(mo - mn);
                mrow[r] = mn;
            }
        }
        __syncthreads();

        float rsum[4] = {0.f, 0.f, 0.f, 0.f};
        #pragma unroll
        for (int i = 0; i < 4; i++) {
            const float mn = mrow[ty * 4 + i];
            #pragma unroll
            for (int j = 0; j < 4; j++) {
                const float p = __expf(sc[i][j] - mn);
                Ps[(ty * 4 + i) * TP + tx * 4 + j] = p;
                rsum[i] += p;
            }
        }
        #pragma unroll
        for (int off = 1; off < 16; off <<= 1)
            #pragma unroll
            for (int i = 0; i < 4; i++)
                rsum[i] += __shfl_xor_sync(0xffffffffu, rsum[i], off);
        if (tx == 0) {
            #pragma unroll
            for (int i = 0; i < 4; i++) {
                const int r = ty * 4 + i;
                lrow[r] = lrow[r] * arow[r] + rsum[i];
            }
        }
        #pragma unroll
        for (int i = 0; i < 4; i++) {
            const float a = arow[ty * 4 + i];
            #pragma unroll
            for (int j = 0; j < 4; j++) { o_r[i][j] *= a; o_i[i][j] *= a; }
        }
        __syncthreads();

        #pragma unroll 4
        for (int jj = 0; jj < 64; jj++) {
            float p[4], vrr[4], vii[4];
            #pragma unroll
            for (int i = 0; i < 4; i++) p[i] = Ps[(ty * 4 + i) * TP + jj];
            #pragma unroll
            for (int j = 0; j < 4; j++) {
                vrr[j] = vs_r[jj * TP + tx * 4 + j];
                vii[j] = vs_i[jj * TP + tx * 4 + j];
            }
            #pragma unroll
            for (int i = 0; i < 4; i++)
                #pragma unroll
                for (int j = 0; j < 4; j++) {
                    o_r[i][j] += p[i] * vrr[j];
                    o_i[i][j] += p[i] * vii[j];
                }
        }
        __syncthreads();
    }

    const int b = bh / HEADS, h = bh % HEADS;
    #pragma unroll
    for (int i = 0; i < 4; i++) {
        const float inv = 1.0f / lrow[ty * 4 + i];
        const int n = q0 + ty * 4 + i;
        #pragma unroll
        for (int j = 0; j < 4; j++) {
            const int d = tx * 4 + j;
            const int idx = (b * Nn + n) * DIMM + h * HD + d;
            g_AOr[idx] = o_r[i][j] * inv;
            g_AOi[idx] = o_i[i][j] * inv;
        }
    }
}

// ---------------- launch ------------------------------------------------------
extern "C" void kernel_launch(void* const* d_in, const int* in_sizes, int n_in,
                              void* d_out, int out_size)
{
    const float* xr  = (const float*)d_in[0];
    const float* xi  = (const float*)d_in[1];
    const float* fr  = (const float*)d_in[2];
    const float* fi  = (const float*)d_in[3];
    const float* wqr = (const float*)d_in[4];
    const float* wqi = (const float*)d_in[5];
    const float* bqr = (const float*)d_in[6];
    const float* bqi = (const float*)d_in[7];
    const float* wor = (const float*)d_in[8];
    const float* woi = (const float*)d_in[9];
    const float* bor = (const float*)d_in[10];
    const float* boi = (const float*)d_in[11];
    float* out = (float*)d_out;

    cudaFuncSetAttribute(qkv_mma_kernel,
                         cudaFuncAttributeMaxDynamicSharedMemorySize, GEMM_SMEM);
    cudaFuncSetAttribute(out_mma_kernel,
                         cudaFuncAttributeMaxDynamicSharedMemorySize, GEMM_SMEM);
    cudaFuncSetAttribute(attn_kernel,
                         cudaFuncAttributeMaxDynamicSharedMemorySize, ATTN_SMEM);

    split_kernel<<<Mtot * DIMM / 1024, 256>>>(xr, 0, Mtot * DIMM);
    split_kernel<<<Mtot * DIMM / 1024, 256>>>(xi, 1, Mtot * DIMM);
    split_kernel<<<E3 * DIMM / 1024, 256>>>(wqr, 2, E3 * DIMM);
    split_kernel<<<E3 * DIMM / 1024, 256>>>(wqi, 3, E3 * DIMM);
    split_kernel<<<DIMM * DIMM / 1024, 256>>>(wor, 4, DIMM * DIMM);
    split_kernel<<<DIMM * DIMM / 1024, 256>>>(woi, 5, DIMM * DIMM);

    qkv_mma_kernel<<<dim3(E3 / 64, Mtot / 128), 256, GEMM_SMEM>>>(bqr, bqi, fr, fi);
    attn_kernel<<<dim3(Nn / 64, Bb * HEADS), 256, ATTN_SMEM>>>();

    split_kernel<<<Mtot * DIMM / 1024, 256>>>(xr, 6, Mtot * DIMM);
    split_kernel<<<Mtot * DIMM / 1024, 256>>>(xr, 7, Mtot * DIMM);

    out_mma_kernel<<<dim3(DIMM / 64, Mtot / 128), 256, GEMM_SMEM>>>(bor, boi, out);
}

// round 4
// speedup vs baseline: 2.8345x; 1.6162x over previous
#include <cuda_runtime.h>
#include <cuda_bf16.h>
#include <stdint.h>
#include <math.h>

#define Bb    2
#define Nn    1024
#define DIMM  1024
#define HEADS 16
#define HD    64
#define Mtot  (Bb * Nn)      // 2048
#define E3    (3 * DIMM)     // 3072

// ---------------- bf16 hi/lo split scratch -----------------------------------
__device__ __nv_bfloat16 g_Xr_h[Mtot * DIMM], g_Xr_l[Mtot * DIMM];
__device__ __nv_bfloat16 g_Xi_h[Mtot * DIMM], g_Xi_l[Mtot * DIMM];
__device__ __nv_bfloat16 g_Wqr_h[E3 * DIMM],  g_Wqr_l[E3 * DIMM];
__device__ __nv_bfloat16 g_Wqi_h[E3 * DIMM],  g_Wqi_l[E3 * DIMM];
__device__ __nv_bfloat16 g_Wor_h[DIMM * DIMM], g_Wor_l[DIMM * DIMM];
__device__ __nv_bfloat16 g_Woi_h[DIMM * DIMM], g_Woi_l[DIMM * DIMM];
__device__ __nv_bfloat16 g_Ar_h[Mtot * DIMM], g_Ar_l[Mtot * DIMM];
__device__ __nv_bfloat16 g_Ai_h[Mtot * DIMM], g_Ai_l[Mtot * DIMM];

// Q/K/V bf16 hi/lo, layout [b*H + h][n][d]
#define QKV_SZ (Bb * HEADS * Nn * HD)
__device__ __nv_bfloat16 g_Qrh[QKV_SZ], g_Qrl[QKV_SZ], g_Qih[QKV_SZ], g_Qil[QKV_SZ];
__device__ __nv_bfloat16 g_Krh[QKV_SZ], g_Krl[QKV_SZ], g_Kih[QKV_SZ], g_Kil[QKV_SZ];
__device__ __nv_bfloat16 g_Vrh[QKV_SZ], g_Vrl[QKV_SZ], g_Vih[QKV_SZ], g_Vil[QKV_SZ];

// ---------------- helpers ----------------------------------------------------
__device__ __forceinline__ uint32_t smem_u32(const void* p) {
    uint32_t a;
    asm("{ .reg .u64 t; cvta.to.shared.u64 t, %1; cvt.u32.u64 %0, t; }"
        : "=r"(a) : "l"(p));
    return a;
}

#define CP16(dst, src) \
    asm volatile("cp.async.cg.shared.global [%0], [%1], 16;" \
                 :: "r"((uint32_t)(dst)), "l"(src) : "memory")
#define CP_COMMIT() asm volatile("cp.async.commit_group;" ::: "memory")
#define CP_WAIT(n)  asm volatile("cp.async.wait_group %0;" :: "n"(n) : "memory")

__device__ __forceinline__ void ldm_x4(uint32_t* r, uint32_t addr) {
    asm volatile("ldmatrix.sync.aligned.m8n8.x4.shared.b16 {%0,%1,%2,%3}, [%4];"
        : "=r"(r[0]), "=r"(r[1]), "=r"(r[2]), "=r"(r[3]) : "r"(addr));
}

__device__ __forceinline__ void ldm_x4_t(uint32_t* r, uint32_t addr) {
    asm volatile("ldmatrix.sync.aligned.m8n8.x4.trans.shared.b16 {%0,%1,%2,%3}, [%4];"
        : "=r"(r[0]), "=r"(r[1]), "=r"(r[2]), "=r"(r[3]) : "r"(addr));
}

__device__ __forceinline__ void mma16816(float* c, const uint32_t* a, const uint32_t* b) {
    asm volatile("mma.sync.aligned.m16n8k16.row.col.f32.bf16.bf16.f32 "
        "{%0,%1,%2,%3}, {%4,%5,%6,%7}, {%8,%9}, {%0,%1,%2,%3};"
        : "+f"(c[0]), "+f"(c[1]), "+f"(c[2]), "+f"(c[3])
        : "r"(a[0]), "r"(a[1]), "r"(a[2]), "r"(a[3]), "r"(b[0]), "r"(b[1]));
}

__device__ __forceinline__ void wsplit(__nv_bfloat16* hi, __nv_bfloat16* lo,
                                       size_t idx, float v) {
    __nv_bfloat16 h = __float2bfloat16(v);
    hi[idx] = h;
    lo[idx] = __float2bfloat16(v - __bfloat162float(h));
}

__device__ __forceinline__ void split2(float a, float b, uint32_t& hi, uint32_t& lo) {
    __nv_bfloat16 ah = __float2bfloat16(a), bh = __float2bfloat16(b);
    float ar = a - __bfloat162float(ah), br = b - __bfloat162float(bh);
    __nv_bfloat162 h; h.x = ah; h.y = bh;
    __nv_bfloat162 l; l.x = __float2bfloat16(ar); l.y = __float2bfloat16(br);
    hi = *(uint32_t*)&h;
    lo = *(uint32_t*)&l;
}

// ---------------- combined input split kernel (one launch) -------------------
__global__ void __launch_bounds__(256) split_all_kernel(
    const float* __restrict__ xr,  const float* __restrict__ xi,
    const float* __restrict__ wqr, const float* __restrict__ wqi,
    const float* __restrict__ wor, const float* __restrict__ woi)
{
    const int blk = blockIdx.x;
    const float* src; __nv_bfloat16 *hi, *lo; int off;
    if      (blk <  2048) { src = xr;  hi = g_Xr_h;  lo = g_Xr_l;  off = blk; }
    else if (blk <  4096) { src = xi;  hi = g_Xi_h;  lo = g_Xi_l;  off = blk - 2048; }
    else if (blk <  7168) { src = wqr; hi = g_Wqr_h; lo = g_Wqr_l; off = blk - 4096; }
    else if (blk < 10240) { src = wqi; hi = g_Wqi_h; lo = g_Wqi_l; off = blk - 7168; }
    else if (blk < 11264) { src = wor; hi = g_Wor_h; lo = g_Wor_l; off = blk - 10240; }
    else                  { src = woi; hi = g_Woi_h; lo = g_Woi_l; off = blk - 11264; }
    const int i = (off * 256 + threadIdx.x) * 4;
    float4 x = *(const float4*)(src + i);
    float xs[4] = {x.x, x.y, x.z, x.w};
    #pragma unroll
    for (int k = 0; k < 4; k++) {
        __nv_bfloat16 h = __float2bfloat16(xs[k]);
        hi[i + k] = h;
        lo[i + k] = __float2bfloat16(xs[k] - __bfloat162float(h));
    }
}

// ---------------- mma.sync complex GEMM core ---------------------------------
#define STG 61440
#define GEMM_SMEM (2 * STG)
#define NCHUNK (DIMM / 32)

__device__ __forceinline__ void stage_load(uint32_t sA,
    const __nv_bfloat16* const* Av, const __nv_bfloat16* const* Bv,
    int m0, int e0, int k0, int tid)
{
    #pragma unroll
    for (int v = 0; v < 4; v++) {
        const __nv_bfloat16* srcA = Av[v] + (size_t)m0 * DIMM + k0;
        uint32_t dstA = sA + v * 10240u;
        #pragma unroll
        for (int t = 0; t < 2; t++) {
            int idx = tid + t * 256;
            int r = idx >> 2, c = idx & 3;
            CP16(dstA + r * 80 + c * 16, srcA + (size_t)r * DIMM + c * 8);
        }
        const __nv_bfloat16* srcB = Bv[v] + (size_t)e0 * DIMM + k0;
        uint32_t dstB = sA + 40960u + v * 5120u;
        {
            int r = tid >> 2, c = tid & 3;
            CP16(dstB + r * 80 + c * 16, srcB + (size_t)r * DIMM + c * 8);
        }
    }
}

__device__ __forceinline__ void gemm_compute(uint32_t ss, int lane, int wm, int wn,
    float accR[2][4][4], float accI[2][4][4])
{
    const uint32_t aRow = (uint32_t)(lane & 15);
    const uint32_t aSel = (uint32_t)(lane >> 4);
    const uint32_t nl   = (uint32_t)((lane & 7) + ((lane >> 4) << 3));
    const uint32_t ksel = (uint32_t)((lane >> 3) & 1);

    #pragma unroll
    for (int ks = 0; ks < 2; ks++) {
        uint32_t Af[4][2][4];
        #pragma unroll
        for (int v = 0; v < 4; v++)
            #pragma unroll
            for (int mf = 0; mf < 2; mf++) {
                uint32_t addr = ss + v * 10240u
                    + (wm * 32 + mf * 16 + aRow) * 80u + aSel * 16u + ks * 32u;
                ldm_x4(Af[v][mf], addr);
            }
        uint32_t nAih[2][4], nAil[2][4];
        #pragma unroll
        for (int mf = 0; mf < 2; mf++)
            #pragma unroll
            for (int q = 0; q < 4; q++) {
                nAih[mf][q] = Af[2][mf][q] ^ 0x80008000u;
                nAil[mf][q] = Af[3][mf][q] ^ 0x80008000u;
            }
        #pragma unroll
        for (int h = 0; h < 2; h++) {
            uint32_t Bf[4][4];
            #pragma unroll
            for (int v = 0; v < 4; v++) {
                uint32_t addr = ss + 40960u + v * 5120u
                    + (wn * 32 + h * 16 + nl) * 80u + ksel * 16u + ks * 32u;
                ldm_x4(Bf[v], addr);
            }
            #pragma unroll
            for (int mf = 0; mf < 2; mf++)
                #pragma unroll
                for (int sub = 0; sub < 2; sub++) {
                    const int nf = h * 2 + sub;
                    const uint32_t* Brh = &Bf[0][sub * 2];
                    const uint32_t* Brl = &Bf[1][sub * 2];
                    const uint32_t* Bih = &Bf[2][sub * 2];
                    const uint32_t* Bil = &Bf[3][sub * 2];
                    float* cr = accR[mf][nf];
                    float* ci = accI[mf][nf];
                    mma16816(cr, Af[0][mf], Brh);
                    mma16816(cr, Af[0][mf], Brl);
                    mma16816(cr, Af[1][mf], Brh);
                    mma16816(cr, nAih[mf],  Bih);
                    mma16816(cr, nAih[mf],  Bil);
                    mma16816(cr, nAil[mf],  Bih);
                    mma16816(ci, Af[0][mf], Bih);
                    mma16816(ci, Af[0][mf], Bil);
                    mma16816(ci, Af[1][mf], Bih);
                    mma16816(ci, Af[2][mf], Brh);
                    mma16816(ci, Af[2][mf], Brl);
                    mma16816(ci, Af[3][mf], Brh);
                }
        }
    }
}

// ---------------- qkv GEMM: fused bias + rotary + split-scatter --------------
__global__ void __launch_bounds__(256, 1) qkv_mma_kernel(
    const float* __restrict__ br, const float* __restrict__ bi,
    const float* __restrict__ fr, const float* __restrict__ fi)
{
    extern __shared__ char smrw[];
    const uint32_t sb = smem_u32(smrw);
    const int tid = threadIdx.x, lane = tid & 31, wid = tid >> 5;
    const int wm = wid >> 1, wn = wid & 1;
    const int e0 = blockIdx.x * 64, m0 = blockIdx.y * 128;

    const __nv_bfloat16* Av[4] = {g_Xr_h, g_Xr_l, g_Xi_h, g_Xi_l};
    const __nv_bfloat16* Bv[4] = {g_Wqr_h, g_Wqr_l, g_Wqi_h, g_Wqi_l};

    float accR[2][4][4] = {}, accI[2][4][4] = {};

    stage_load(sb, Av, Bv, m0, e0, 0, tid);
    CP_COMMIT();

    #pragma unroll 1
    for (int c = 0; c < NCHUNK; c++) {
        const int s = c & 1;
        if (c + 1 < NCHUNK) {
            stage_load(sb + (s ^ 1) * STG, Av, Bv, m0, e0, (c + 1) * 32, tid);
            CP_COMMIT();
            CP_WAIT(1);
        } else {
            CP_WAIT(0);
        }
        __syncthreads();
        gemm_compute(sb + s * STG, lane, wm, wn, accR, accI);
        __syncthreads();
    }

    #pragma unroll
    for (int mf = 0; mf < 2; mf++)
        #pragma unroll
        for (int nf = 0; nf < 4; nf++)
            #pragma unroll
            for (int rp = 0; rp < 2; rp++)
                #pragma unroll
                for (int cp = 0; cp < 2; cp++) {
                    const int m = m0 + wm * 32 + mf * 16 + (lane >> 2) + rp * 8;
                    const int e = e0 + wn * 32 + nf * 8 + (lane & 3) * 2 + cp;
                    const float vr = accR[mf][nf][rp * 2 + cp] + br[e];
                    const float vi = accI[mf][nf][rp * 2 + cp] + bi[e];
                    const int b = m >> 10;
                    const int n = m & 1023;
                    const int h = e / (HD * 3);
                    const int rem = e % (HD * 3);
                    const int d = rem / 3;
                    const int which = rem % 3;
                    const size_t idx = ((size_t)(b * HEADS + h) * Nn + n) * HD + d;
                    if (which == 2) {
                        wsplit(g_Vrh, g_Vrl, idx, vr);
                        wsplit(g_Vih, g_Vil, idx, vi);
                    } else {
                        const float frv = fr[n * HD + d];
                        const float fiv = fi[n * HD + d];
                        const float rr = vr * frv - vi * fiv;
                        const float ii = vr * fiv + vi * frv;
                        if (which == 0) {
                            wsplit(g_Qrh, g_Qrl, idx, rr);
                            wsplit(g_Qih, g_Qil, idx, ii);
                        } else {
                            wsplit(g_Krh, g_Krl, idx, rr);
                            wsplit(g_Kih, g_Kil, idx, ii);
                        }
                    }
                }
}

// ---------------- output GEMM ------------------------------------------------
__global__ void __launch_bounds__(256, 1) out_mma_kernel(
    const float* __restrict__ br, const float* __restrict__ bi,
    float* __restrict__ out)
{
    extern __shared__ char smrw[];
    const uint32_t sb = smem_u32(smrw);
    const int tid = threadIdx.x, lane = tid & 31, wid = tid >> 5;
    const int wm = wid >> 1, wn = wid & 1;
    const int e0 = blockIdx.x * 64, m0 = blockIdx.y * 128;

    const __nv_bfloat16* Av[4] = {g_Ar_h, g_Ar_l, g_Ai_h, g_Ai_l};
    const __nv_bfloat16* Bv[4] = {g_Wor_h, g_Wor_l, g_Woi_h, g_Woi_l};

    float accR[2][4][4] = {}, accI[2][4][4] = {};

    stage_load(sb, Av, Bv, m0, e0, 0, tid);
    CP_COMMIT();

    #pragma unroll 1
    for (int c = 0; c < NCHUNK; c++) {
        const int s = c & 1;
        if (c + 1 < NCHUNK) {
            stage_load(sb + (s ^ 1) * STG, Av, Bv, m0, e0, (c + 1) * 32, tid);
            CP_COMMIT();
            CP_WAIT(1);
        } else {
            CP_WAIT(0);
        }
        __syncthreads();
        gemm_compute(sb + s * STG, lane, wm, wn, accR, accI);
        __syncthreads();
    }

    #pragma unroll
    for (int mf = 0; mf < 2; mf++)
        #pragma unroll
        for (int nf = 0; nf < 4; nf++)
            #pragma unroll
            for (int rp = 0; rp < 2; rp++)
                #pragma unroll
                for (int cp = 0; cp < 2; cp++) {
                    const int m = m0 + wm * 32 + mf * 16 + (lane >> 2) + rp * 8;
                    const int e = e0 + wn * 32 + nf * 8 + (lane & 3) * 2 + cp;
                    out[(size_t)m * DIMM + e] = accR[mf][nf][rp * 2 + cp] + br[e];
                    out[(size_t)Mtot * DIMM + (size_t)m * DIMM + e] =
                        accI[mf][nf][rp * 2 + cp] + bi[e];
                }
}

// ---------------- tensor-core flash attention --------------------------------
// 128-query tile, 8 warps x 16 rows, 64-key iterations, double-buffered K/V.
// smem pitch 144 B/row (conflict-free ldmatrix).
#define PCH 144
#define VAR_Q  18432           // 128 rows * 144
#define VAR_KV 9216            // 64 rows * 144
#define SK_OFF 73728
#define SV_OFF 147456
#define STG_KV 36864
#define ATTN_SMEM 221184

__device__ __forceinline__ void load_kv(uint32_t sb,
    const __nv_bfloat16* const* Kv, const __nv_bfloat16* const* Vv,
    int k0, int s, int tid)
{
    #pragma unroll
    for (int v = 0; v < 4; v++)
        #pragma unroll
        for (int t = 0; t < 2; t++) {
            int i = tid + t * 256;
            int r = i >> 3, c = i & 7;
            CP16(sb + SK_OFF + s * STG_KV + v * VAR_KV + r * PCH + c * 16,
                 Kv[v] + (size_t)(k0 + r) * HD + c * 8);
            CP16(sb + SV_OFF + s * STG_KV + v * VAR_KV + r * PCH + c * 16,
                 Vv[v] + (size_t)(k0 + r) * HD + c * 8);
        }
}

__global__ void __launch_bounds__(256, 1) attn_mma_kernel()
{
    extern __shared__ char smrw[];
    const uint32_t sb = smem_u32(smrw);
    const int tid = threadIdx.x, lane = tid & 31, wid = tid >> 5;
    const int bh = blockIdx.y, q0 = blockIdx.x * 128;
    const size_t base = (size_t)bh * Nn * HD;

    const __nv_bfloat16* Qv[4] = {g_Qrh + base, g_Qrl + base, g_Qih + base, g_Qil + base};
    const __nv_bfloat16* Kv[4] = {g_Krh + base, g_Krl + base, g_Kih + base, g_Kil + base};
    const __nv_bfloat16* Vv[4] = {g_Vrh + base, g_Vrl + base, g_Vih + base, g_Vil + base};

    // load Q tile + KV stage 0
    #pragma unroll
    for (int v = 0; v < 4; v++)
        #pragma unroll
        for (int t = 0; t < 4; t++) {
            int i = tid + t * 256;
            int r = i >> 3, c = i & 7;
            CP16(sb + v * VAR_Q + r * PCH + c * 16, Qv[v] + (size_t)(q0 + r) * HD + c * 8);
        }
    load_kv(sb, Kv, Vv, 0, 0, tid);
    CP_COMMIT();

    float oR[8][4] = {}, oI[8][4] = {};
    float m0 = -1e30f, m1 = -1e30f, l0 = 0.f, l1 = 0.f;
    const int r0 = wid * 16;

    #pragma unroll 1
    for (int kt = 0; kt < 16; kt++) {
        const int s = kt & 1;
        if (kt + 1 < 16) {
            load_kv(sb, Kv, Vv, (kt + 1) * 64, s ^ 1, tid);
            CP_COMMIT();
            CP_WAIT(1);
        } else {
            CP_WAIT(0);
        }
        __syncthreads();

        const uint32_t sK = sb + SK_OFF + s * STG_KV;
        const uint32_t sV = sb + SV_OFF + s * STG_KV;

        // ---- S = Q . conj(K), hi/lo split, 2 accumulators w/ sign flips ----
        float sR[8][4] = {}, sI[8][4] = {};
        #pragma unroll
        for (int ks = 0; ks < 4; ks++) {
            uint32_t Qf[4][4];
            const uint32_t qa = sb + (r0 + (lane & 15)) * PCH + (lane >> 4) * 16 + ks * 32;
            #pragma unroll
            for (int v = 0; v < 4; v++) ldm_x4(Qf[v], qa + v * VAR_Q);
            uint32_t nQrh[4], nQrl[4];
            #pragma unroll
            for (int q = 0; q < 4; q++) {
                nQrh[q] = Qf[0][q] ^ 0x80008000u;
                nQrl[q] = Qf[1][q] ^ 0x80008000u;
            }
            #pragma unroll
            for (int np = 0; np < 4; np++) {
                uint32_t Kf[4][4];
                const uint32_t ka = sK + (np * 16 + (lane >> 4) * 8 + (lane & 7)) * PCH
                                    + ((lane >> 3) & 1) * 16 + ks * 32;
                #pragma unroll
                for (int v = 0; v < 4; v++) ldm_x4(Kf[v], ka + v * VAR_KV);
                #pragma unroll
                for (int sub = 0; sub < 2; sub++) {
                    const int nt = np * 2 + sub;
                    const uint32_t* Krh = &Kf[0][sub * 2];
                    const uint32_t* Krl = &Kf[1][sub * 2];
                    const uint32_t* Kih = &Kf[2][sub * 2];
                    const uint32_t* Kil = &Kf[3][sub * 2];
                    // real = QrKr + QiKi
                    mma16816(sR[nt], Qf[0], Krh);
                    mma16816(sR[nt], Qf[0], Krl);
                    mma16816(sR[nt], Qf[1], Krh);
                    mma16816(sR[nt], Qf[2], Kih);
                    mma16816(sR[nt], Qf[2], Kil);
                    mma16816(sR[nt], Qf[3], Kih);
                    // imag = QiKr - QrKi
                    mma16816(sI[nt], Qf[2], Krh);
                    mma16816(sI[nt], Qf[2], Krl);
                    mma16816(sI[nt], Qf[3], Krh);
                    mma16816(sI[nt], nQrh,  Kih);
                    mma16816(sI[nt], nQrh,  Kil);
                    mma16816(sI[nt], nQrl,  Kih);
                }
            }
        }

        // ---- online softmax on scaled |S| ----
        float vm0 = -1e30f, vm1 = -1e30f;
        #pragma unroll
        for (int nt = 0; nt < 8; nt++)
            #pragma unroll
            for (int p = 0; p < 4; p++) {
                const float v = 0.125f * sqrtf(sR[nt][p] * sR[nt][p] + sI[nt][p] * sI[nt][p]);
                sR[nt][p] = v;
                if (p < 2) vm0 = fmaxf(vm0, v); else vm1 = fmaxf(vm1, v);
            }
        vm0 = fmaxf(vm0, __shfl_xor_sync(0xffffffffu, vm0, 1));
        vm0 = fmaxf(vm0, __shfl_xor_sync(0xffffffffu, vm0, 2));
        vm1 = fmaxf(vm1, __shfl_xor_sync(0xffffffffu, vm1, 1));
        vm1 = fmaxf(vm1, __shfl_xor_sync(0xffffffffu, vm1, 2));
        const float mn0 = fmaxf(m0, vm0), mn1 = fmaxf(m1, vm1);
        const float a0 = __expf(m0 - mn0), a1 = __expf(m1 - mn1);
        m0 = mn0; m1 = mn1;
        #pragma unroll
        for (int nt = 0; nt < 8; nt++)
            #pragma unroll
            for (int p = 0; p < 4; p++) {
                const float al = (p < 2) ? a0 : a1;
                oR[nt][p] *= al;
                oI[nt][p] *= al;
            }
        float s0 = 0.f, s1 = 0.f;
        #pragma unroll
        for (int nt = 0; nt < 8; nt++)
            #pragma unroll
            for (int p = 0; p < 4; p++) {
                const float pv = __expf(sR[nt][p] - ((p < 2) ? mn0 : mn1));
                sR[nt][p] = pv;
                if (p < 2) s0 += pv; else s1 += pv;
            }
        s0 += __shfl_xor_sync(0xffffffffu, s0, 1);
        s0 += __shfl_xor_sync(0xffffffffu, s0, 2);
        s1 += __shfl_xor_sync(0xffffffffu, s1, 1);
        s1 += __shfl_xor_sync(0xffffffffu, s1, 2);
        l0 = l0 * a0 + s0;
        l1 = l1 * a1 + s1;

        // ---- pack P into A-fragments (hi/lo) ----
        uint32_t Ph[4][4], Pl[4][4];
        #pragma unroll
        for (int j = 0; j < 4; j++) {
            const int t0 = 2 * j, t1 = 2 * j + 1;
            split2(sR[t0][0], sR[t0][1], Ph[j][0], Pl[j][0]);
            split2(sR[t0][2], sR[t0][3], Ph[j][1], Pl[j][1]);
            split2(sR[t1][0], sR[t1][1], Ph[j][2], Pl[j][2]);
            split2(sR[t1][2], sR[t1][3], Ph[j][3], Pl[j][3]);
        }

        // ---- O += P @ V (ldmatrix.trans on V) ----
        #pragma unroll
        for (int j = 0; j < 4; j++) {
            #pragma unroll
            for (int g = 0; g < 4; g++) {
                uint32_t Vf[4][4];
                const uint32_t va = sV + (j * 16 + ((lane >> 3) & 1) * 8 + (lane & 7)) * PCH
                                    + (lane >> 4) * 16 + g * 32;
                #pragma unroll
                for (int v = 0; v < 4; v++) ldm_x4_t(Vf[v], va + v * VAR_KV);
                #pragma unroll
                for (int sub = 0; sub < 2; sub++) {
                    const int nt = g * 2 + sub;
                    const uint32_t* Vrh = &Vf[0][sub * 2];
                    const uint32_t* Vrl = &Vf[1][sub * 2];
                    const uint32_t* Vih = &Vf[2][sub * 2];
                    const uint32_t* Vil = &Vf[3][sub * 2];
                    mma16816(oR[nt], Ph[j], Vrh);
                    mma16816(oR[nt], Pl[j], Vrh);
                    mma16816(oR[nt], Ph[j], Vrl);
                    mma16816(oI[nt], Ph[j], Vih);
                    mma16816(oI[nt], Pl[j], Vih);
                    mma16816(oI[nt], Ph[j], Vil);
                }
            }
        }
        __syncthreads();
    }

    // ---- normalize + write AO as bf16 hi/lo, layout [b][n][h*64+d] ----
    const float inv0 = 1.0f / l0, inv1 = 1.0f / l1;
    const int b = bh / HEADS, h = bh % HEADS;
    #pragma unroll
    for (int nt = 0; nt < 8; nt++)
        #pragma unroll
        for (int p = 0; p < 4; p++) {
            const int n = q0 + r0 + (lane >> 2) + (p >> 1) * 8;
            const int d = nt * 8 + (lane & 3) * 2 + (p & 1);
            const float inv = (p < 2) ? inv0 : inv1;
            const size_t idx = ((size_t)(b * Nn + n)) * DIMM + h * HD + d;
            wsplit(g_Ar_h, g_Ar_l, idx, oR[nt][p] * inv);
            wsplit(g_Ai_h, g_Ai_l, idx, oI[nt][p] * inv);
        }
}

// ---------------- launch ------------------------------------------------------
extern "C" void kernel_launch(void* const* d_in, const int* in_sizes, int n_in,
                              void* d_out, int out_size)
{
    const float* xr  = (const float*)d_in[0];
    const float* xi  = (const float*)d_in[1];
    const float* fr  = (const float*)d_in[2];
    const float* fi  = (const float*)d_in[3];
    const float* wqr = (const float*)d_in[4];
    const float* wqi = (const float*)d_in[5];
    const float* bqr = (const float*)d_in[6];
    const float* bqi = (const float*)d_in[7];
    const float* wor = (const float*)d_in[8];
    const float* woi = (const float*)d_in[9];
    const float* bor = (const float*)d_in[10];
    const float* boi = (const float*)d_in[11];
    float* out = (float*)d_out;

    cudaFuncSetAttribute(qkv_mma_kernel,
                         cudaFuncAttributeMaxDynamicSharedMemorySize, GEMM_SMEM);
    cudaFuncSetAttribute(out_mma_kernel,
                         cudaFuncAttributeMaxDynamicSharedMemorySize, GEMM_SMEM);
    cudaFuncSetAttribute(attn_mma_kernel,
                         cudaFuncAttributeMaxDynamicSharedMemorySize, ATTN_SMEM);

    split_all_kernel<<<12288, 256>>>(xr, xi, wqr, wqi, wor, woi);
    qkv_mma_kernel<<<dim3(E3 / 64, Mtot / 128), 256, GEMM_SMEM>>>(bqr, bqi, fr, fi);
    attn_mma_kernel<<<dim3(Nn / 128, Bb * HEADS), 256, ATTN_SMEM>>>();
    out_mma_kernel<<<dim3(DIMM / 64, Mtot / 128), 256, GEMM_SMEM>>>(bor, boi, out);
}

// round 5
// speedup vs baseline: 3.0345x; 1.0706x over previous
#include <cuda_runtime.h>
#include <cuda_bf16.h>
#include <stdint.h>
#include <math.h>

#define Bb    2
#define Nn    1024
#define DIMM  1024
#define HEADS 16
#define HD    64
#define Mtot  (Bb * Nn)      // 2048
#define E3    (3 * DIMM)     // 3072

// ---------------- bf16 hi/lo split scratch -----------------------------------
__device__ __nv_bfloat16 g_Xr_h[Mtot * DIMM], g_Xr_l[Mtot * DIMM];
__device__ __nv_bfloat16 g_Xi_h[Mtot * DIMM], g_Xi_l[Mtot * DIMM];
__device__ __nv_bfloat16 g_Wqr_h[E3 * DIMM],  g_Wqr_l[E3 * DIMM];
__device__ __nv_bfloat16 g_Wqi_h[E3 * DIMM],  g_Wqi_l[E3 * DIMM];
__device__ __nv_bfloat16 g_Wor_h[DIMM * DIMM], g_Wor_l[DIMM * DIMM];
__device__ __nv_bfloat16 g_Woi_h[DIMM * DIMM], g_Woi_l[DIMM * DIMM];
__device__ __nv_bfloat16 g_Ar_h[Mtot * DIMM], g_Ar_l[Mtot * DIMM];
__device__ __nv_bfloat16 g_Ai_h[Mtot * DIMM], g_Ai_l[Mtot * DIMM];

// Q/K/V bf16 hi/lo, layout [b*H + h][n][d]
#define QKV_SZ (Bb * HEADS * Nn * HD)
__device__ __nv_bfloat16 g_Qrh[QKV_SZ], g_Qrl[QKV_SZ], g_Qih[QKV_SZ], g_Qil[QKV_SZ];
__device__ __nv_bfloat16 g_Krh[QKV_SZ], g_Krl[QKV_SZ], g_Kih[QKV_SZ], g_Kil[QKV_SZ];
__device__ __nv_bfloat16 g_Vrh[QKV_SZ], g_Vrl[QKV_SZ], g_Vih[QKV_SZ], g_Vil[QKV_SZ];

// ---------------- helpers ----------------------------------------------------
__device__ __forceinline__ uint32_t smem_u32(const void* p) {
    uint32_t a;
    asm("{ .reg .u64 t; cvta.to.shared.u64 t, %1; cvt.u32.u64 %0, t; }"
        : "=r"(a) : "l"(p));
    return a;
}

#define CP16(dst, src) \
    asm volatile("cp.async.cg.shared.global [%0], [%1], 16;" \
                 :: "r"((uint32_t)(dst)), "l"(src) : "memory")
#define CP_COMMIT() asm volatile("cp.async.commit_group;" ::: "memory")
#define CP_WAIT(n)  asm volatile("cp.async.wait_group %0;" :: "n"(n) : "memory")

__device__ __forceinline__ void ldm_x4(uint32_t* r, uint32_t addr) {
    asm volatile("ldmatrix.sync.aligned.m8n8.x4.shared.b16 {%0,%1,%2,%3}, [%4];"
        : "=r"(r[0]), "=r"(r[1]), "=r"(r[2]), "=r"(r[3]) : "r"(addr));
}

__device__ __forceinline__ void ldm_x4_t(uint32_t* r, uint32_t addr) {
    asm volatile("ldmatrix.sync.aligned.m8n8.x4.trans.shared.b16 {%0,%1,%2,%3}, [%4];"
        : "=r"(r[0]), "=r"(r[1]), "=r"(r[2]), "=r"(r[3]) : "r"(addr));
}

__device__ __forceinline__ void mma16816(float* c, const uint32_t* a, const uint32_t* b) {
    asm volatile("mma.sync.aligned.m16n8k16.row.col.f32.bf16.bf16.f32 "
        "{%0,%1,%2,%3}, {%4,%5,%6,%7}, {%8,%9}, {%0,%1,%2,%3};"
        : "+f"(c[0]), "+f"(c[1]), "+f"(c[2]), "+f"(c[3])
        : "r"(a[0]), "r"(a[1]), "r"(a[2]), "r"(a[3]), "r"(b[0]), "r"(b[1]));
}

__device__ __forceinline__ void wsplit(__nv_bfloat16* hi, __nv_bfloat16* lo,
                                       size_t idx, float v) {
    __nv_bfloat16 h = __float2bfloat16(v);
    hi[idx] = h;
    lo[idx] = __float2bfloat16(v - __bfloat162float(h));
}

__device__ __forceinline__ void split2(float a, float b, uint32_t& hi, uint32_t& lo) {
    __nv_bfloat16 ah = __float2bfloat16(a), bh = __float2bfloat16(b);
    float ar = a - __bfloat162float(ah), br = b - __bfloat162float(bh);
    __nv_bfloat162 h; h.x = ah; h.y = bh;
    __nv_bfloat162 l; l.x = __float2bfloat16(ar); l.y = __float2bfloat16(br);
    hi = *(uint32_t*)&h;
    lo = *(uint32_t*)&l;
}

// ---------------- combined input split kernel (vectorized stores) ------------
__global__ void __launch_bounds__(256) split_all_kernel(
    const float* __restrict__ xr,  const float* __restrict__ xi,
    const float* __restrict__ wqr, const float* __restrict__ wqi,
    const float* __restrict__ wor, const float* __restrict__ woi)
{
    const int blk = blockIdx.x;
    const float* src; __nv_bfloat16 *hi, *lo; int off;
    if      (blk <  2048) { src = xr;  hi = g_Xr_h;  lo = g_Xr_l;  off = blk; }
    else if (blk <  4096) { src = xi;  hi = g_Xi_h;  lo = g_Xi_l;  off = blk - 2048; }
    else if (blk <  7168) { src = wqr; hi = g_Wqr_h; lo = g_Wqr_l; off = blk - 4096; }
    else if (blk < 10240) { src = wqi; hi = g_Wqi_h; lo = g_Wqi_l; off = blk - 7168; }
    else if (blk < 11264) { src = wor; hi = g_Wor_h; lo = g_Wor_l; off = blk - 10240; }
    else                  { src = woi; hi = g_Woi_h; lo = g_Woi_l; off = blk - 11264; }
    const int i = (off * 256 + threadIdx.x) * 4;
    float4 x = *(const float4*)(src + i);
    uint32_t h01, l01, h23, l23;
    split2(x.x, x.y, h01, l01);
    split2(x.z, x.w, h23, l23);
    *(uint2*)(hi + i) = make_uint2(h01, h23);
    *(uint2*)(lo + i) = make_uint2(l01, l23);
}

// ---------------- mma.sync complex GEMM core ---------------------------------
// Block 128(m) x 128(n), 8 warps as 4(m) x 2(n), warp tile 32x64.
// K-chunk 32, double-buffered smem, pitch 80 B (conflict-free ldmatrix).
// Stage layout: A[v] at v*10240 (128 rows x 80B), B[v] at 40960 + v*10240.
#define STG 81920
#define GEMM_SMEM (2 * STG)
#define NCHUNK (DIMM / 32)

__device__ __forceinline__ void stage_load(uint32_t sA,
    const __nv_bfloat16* const* Av, const __nv_bfloat16* const* Bv,
    int m0, int e0, int k0, int tid)
{
    #pragma unroll
    for (int v = 0; v < 4; v++) {
        const __nv_bfloat16* srcA = Av[v] + (size_t)m0 * DIMM + k0;
        uint32_t dstA = sA + v * 10240u;
        #pragma unroll
        for (int t = 0; t < 2; t++) {
            int idx = tid + t * 256;
            int r = idx >> 2, c = idx & 3;
            CP16(dstA + r * 80 + c * 16, srcA + (size_t)r * DIMM + c * 8);
        }
        const __nv_bfloat16* srcB = Bv[v] + (size_t)e0 * DIMM + k0;
        uint32_t dstB = sA + 40960u + v * 10240u;
        #pragma unroll
        for (int t = 0; t < 2; t++) {
            int idx = tid + t * 256;
            int r = idx >> 2, c = idx & 3;
            CP16(dstB + r * 80 + c * 16, srcB + (size_t)r * DIMM + c * 8);
        }
    }
}

__device__ __forceinline__ void gemm_compute(uint32_t ss, int lane, int wm, int wn,
    float accR[2][8][4], float accI[2][8][4])
{
    const uint32_t aRow = (uint32_t)(lane & 15);
    const uint32_t aSel = (uint32_t)(lane >> 4);
    const uint32_t nl   = (uint32_t)((lane & 7) + ((lane >> 4) << 3));
    const uint32_t ksel = (uint32_t)((lane >> 3) & 1);

    #pragma unroll
    for (int ks = 0; ks < 2; ks++) {
        uint32_t Af[4][2][4];
        #pragma unroll
        for (int v = 0; v < 4; v++)
            #pragma unroll
            for (int mf = 0; mf < 2; mf++) {
                uint32_t addr = ss + v * 10240u
                    + (wm * 32 + mf * 16 + aRow) * 80u + aSel * 16u + ks * 32u;
                ldm_x4(Af[v][mf], addr);
            }
        uint32_t nAih[2][4], nAil[2][4];
        #pragma unroll
        for (int mf = 0; mf < 2; mf++)
            #pragma unroll
            for (int q = 0; q < 4; q++) {
                nAih[mf][q] = Af[2][mf][q] ^ 0x80008000u;
                nAil[mf][q] = Af[3][mf][q] ^ 0x80008000u;
            }
        #pragma unroll
        for (int h = 0; h < 4; h++) {
            uint32_t Bf[4][4];
            #pragma unroll
            for (int v = 0; v < 4; v++) {
                uint32_t addr = ss + 40960u + v * 10240u
                    + (wn * 64 + h * 16 + nl) * 80u + ksel * 16u + ks * 32u;
                ldm_x4(Bf[v], addr);
            }
            #pragma unroll
            for (int mf = 0; mf < 2; mf++)
                #pragma unroll
                for (int sub = 0; sub < 2; sub++) {
                    const int nf = h * 2 + sub;
                    const uint32_t* Brh = &Bf[0][sub * 2];
                    const uint32_t* Brl = &Bf[1][sub * 2];
                    const uint32_t* Bih = &Bf[2][sub * 2];
                    const uint32_t* Bil = &Bf[3][sub * 2];
                    float* cr = accR[mf][nf];
                    float* ci = accI[mf][nf];
                    mma16816(cr, Af[0][mf], Brh);
                    mma16816(cr, Af[0][mf], Brl);
                    mma16816(cr, Af[1][mf], Brh);
                    mma16816(cr, nAih[mf],  Bih);
                    mma16816(cr, nAih[mf],  Bil);
                    mma16816(cr, nAil[mf],  Bih);
                    mma16816(ci, Af[0][mf], Bih);
                    mma16816(ci, Af[0][mf], Bil);
                    mma16816(ci, Af[1][mf], Bih);
                    mma16816(ci, Af[2][mf], Brh);
                    mma16816(ci, Af[2][mf], Brl);
                    mma16816(ci, Af[3][mf], Brh);
                }
        }
    }
}

// ---------------- qkv GEMM: fused bias + rotary + split-scatter --------------
__global__ void __launch_bounds__(256, 1) qkv_mma_kernel(
    const float* __restrict__ br, const float* __restrict__ bi,
    const float* __restrict__ fr, const float* __restrict__ fi)
{
    extern __shared__ char smrw[];
    const uint32_t sb = smem_u32(smrw);
    const int tid = threadIdx.x, lane = tid & 31, wid = tid >> 5;
    const int wm = wid >> 1, wn = wid & 1;
    const int e0 = blockIdx.x * 128, m0 = blockIdx.y * 128;

    const __nv_bfloat16* Av[4] = {g_Xr_h, g_Xr_l, g_Xi_h, g_Xi_l};
    const __nv_bfloat16* Bv[4] = {g_Wqr_h, g_Wqr_l, g_Wqi_h, g_Wqi_l};

    float accR[2][8][4] = {}, accI[2][8][4] = {};

    stage_load(sb, Av, Bv, m0, e0, 0, tid);
    CP_COMMIT();

    #pragma unroll 1
    for (int c = 0; c < NCHUNK; c++) {
        const int s = c & 1;
        if (c + 1 < NCHUNK) {
            stage_load(sb + (s ^ 1) * STG, Av, Bv, m0, e0, (c + 1) * 32, tid);
            CP_COMMIT();
            CP_WAIT(1);
        } else {
            CP_WAIT(0);
        }
        __syncthreads();
        gemm_compute(sb + s * STG, lane, wm, wn, accR, accI);
        __syncthreads();
    }

    #pragma unroll
    for (int mf = 0; mf < 2; mf++)
        #pragma unroll
        for (int nf = 0; nf < 8; nf++)
            #pragma unroll
            for (int rp = 0; rp < 2; rp++)
                #pragma unroll
                for (int cp = 0; cp < 2; cp++) {
                    const int m = m0 + wm * 32 + mf * 16 + (lane >> 2) + rp * 8;
                    const int e = e0 + wn * 64 + nf * 8 + (lane & 3) * 2 + cp;
                    const float vr = accR[mf][nf][rp * 2 + cp] + br[e];
                    const float vi = accI[mf][nf][rp * 2 + cp] + bi[e];
                    const int b = m >> 10;
                    const int n = m & 1023;
                    const int h = e / (HD * 3);
                    const int rem = e % (HD * 3);
                    const int d = rem / 3;
                    const int which = rem % 3;
                    const size_t idx = ((size_t)(b * HEADS + h) * Nn + n) * HD + d;
                    if (which == 2) {
                        wsplit(g_Vrh, g_Vrl, idx, vr);
                        wsplit(g_Vih, g_Vil, idx, vi);
                    } else {
                        const float frv = fr[n * HD + d];
                        const float fiv = fi[n * HD + d];
                        const float rr = vr * frv - vi * fiv;
                        const float ii = vr * fiv + vi * frv;
                        if (which == 0) {
                            wsplit(g_Qrh, g_Qrl, idx, rr);
                            wsplit(g_Qih, g_Qil, idx, ii);
                        } else {
                            wsplit(g_Krh, g_Krl, idx, rr);
                            wsplit(g_Kih, g_Kil, idx, ii);
                        }
                    }
                }
}

// ---------------- output GEMM ------------------------------------------------
__global__ void __launch_bounds__(256, 1) out_mma_kernel(
    const float* __restrict__ br, const float* __restrict__ bi,
    float* __restrict__ out)
{
    extern __shared__ char smrw[];
    const uint32_t sb = smem_u32(smrw);
    const int tid = threadIdx.x, lane = tid & 31, wid = tid >> 5;
    const int wm = wid >> 1, wn = wid & 1;
    const int e0 = blockIdx.x * 128, m0 = blockIdx.y * 128;

    const __nv_bfloat16* Av[4] = {g_Ar_h, g_Ar_l, g_Ai_h, g_Ai_l};
    const __nv_bfloat16* Bv[4] = {g_Wor_h, g_Wor_l, g_Woi_h, g_Woi_l};

    float accR[2][8][4] = {}, accI[2][8][4] = {};

    stage_load(sb, Av, Bv, m0, e0, 0, tid);
    CP_COMMIT();

    #pragma unroll 1
    for (int c = 0; c < NCHUNK; c++) {
        const int s = c & 1;
        if (c + 1 < NCHUNK) {
            stage_load(sb + (s ^ 1) * STG, Av, Bv, m0, e0, (c + 1) * 32, tid);
            CP_COMMIT();
            CP_WAIT(1);
        } else {
            CP_WAIT(0);
        }
        __syncthreads();
        gemm_compute(sb + s * STG, lane, wm, wn, accR, accI);
        __syncthreads();
    }

    #pragma unroll
    for (int mf = 0; mf < 2; mf++)
        #pragma unroll
        for (int nf = 0; nf < 8; nf++)
            #pragma unroll
            for (int rp = 0; rp < 2; rp++)
                #pragma unroll
                for (int cp = 0; cp < 2; cp++) {
                    const int m = m0 + wm * 32 + mf * 16 + (lane >> 2) + rp * 8;
                    const int e = e0 + wn * 64 + nf * 8 + (lane & 3) * 2 + cp;
                    out[(size_t)m * DIMM + e] = accR[mf][nf][rp * 2 + cp] + br[e];
                    out[(size_t)Mtot * DIMM + (size_t)m * DIMM + e] =
                        accI[mf][nf][rp * 2 + cp] + bi[e];
                }
}

// ---------------- tensor-core flash attention --------------------------------
#define PCH 144
#define VAR_Q  18432
#define VAR_KV 9216
#define SK_OFF 73728
#define SV_OFF 147456
#define STG_KV 36864
#define ATTN_SMEM 221184

__device__ __forceinline__ void load_kv(uint32_t sb,
    const __nv_bfloat16* const* Kv, const __nv_bfloat16* const* Vv,
    int k0, int s, int tid)
{
    #pragma unroll
    for (int v = 0; v < 4; v++)
        #pragma unroll
        for (int t = 0; t < 2; t++) {
            int i = tid + t * 256;
            int r = i >> 3, c = i & 7;
            CP16(sb + SK_OFF + s * STG_KV + v * VAR_KV + r * PCH + c * 16,
                 Kv[v] + (size_t)(k0 + r) * HD + c * 8);
            CP16(sb + SV_OFF + s * STG_KV + v * VAR_KV + r * PCH + c * 16,
                 Vv[v] + (size_t)(k0 + r) * HD + c * 8);
        }
}

__global__ void __launch_bounds__(256, 1) attn_mma_kernel()
{
    extern __shared__ char smrw[];
    const uint32_t sb = smem_u32(smrw);
    const int tid = threadIdx.x, lane = tid & 31, wid = tid >> 5;
    const int bh = blockIdx.y, q0 = blockIdx.x * 128;
    const size_t base = (size_t)bh * Nn * HD;

    const __nv_bfloat16* Qv[4] = {g_Qrh + base, g_Qrl + base, g_Qih + base, g_Qil + base};
    const __nv_bfloat16* Kv[4] = {g_Krh + base, g_Krl + base, g_Kih + base, g_Kil + base};
    const __nv_bfloat16* Vv[4] = {g_Vrh + base, g_Vrl + base, g_Vih + base, g_Vil + base};

    #pragma unroll
    for (int v = 0; v < 4; v++)
        #pragma unroll
        for (int t = 0; t < 4; t++) {
            int i = tid + t * 256;
            int r = i >> 3, c = i & 7;
            CP16(sb + v * VAR_Q + r * PCH + c * 16, Qv[v] + (size_t)(q0 + r) * HD + c * 8);
        }
    load_kv(sb, Kv, Vv, 0, 0, tid);
    CP_COMMIT();

    float oR[8][4] = {}, oI[8][4] = {};
    float m0 = -1e30f, m1 = -1e30f, l0 = 0.f, l1 = 0.f;
    const int r0 = wid * 16;

    #pragma unroll 1
    for (int kt = 0; kt < 16; kt++) {
        const int s = kt & 1;
        if (kt + 1 < 16) {
            load_kv(sb, Kv, Vv, (kt + 1) * 64, s ^ 1, tid);
            CP_COMMIT();
            CP_WAIT(1);
        } else {
            CP_WAIT(0);
        }
        __syncthreads();

        const uint32_t sK = sb + SK_OFF + s * STG_KV;
        const uint32_t sV = sb + SV_OFF + s * STG_KV;

        float sR[8][4] = {}, sI[8][4] = {};
        #pragma unroll
        for (int ks = 0; ks < 4; ks++) {
            uint32_t Qf[4][4];
            const uint32_t qa = sb + (r0 + (lane & 15)) * PCH + (lane >> 4) * 16 + ks * 32;
            #pragma unroll
            for (int v = 0; v < 4; v++) ldm_x4(Qf[v], qa + v * VAR_Q);
            uint32_t nQrh[4], nQrl[4];
            #pragma unroll
            for (int q = 0; q < 4; q++) {
                nQrh[q] = Qf[0][q] ^ 0x80008000u;
                nQrl[q] = Qf[1][q] ^ 0x80008000u;
            }
            #pragma unroll
            for (int np = 0; np < 4; np++) {
                uint32_t Kf[4][4];
                const uint32_t ka = sK + (np * 16 + (lane >> 4) * 8 + (lane & 7)) * PCH
                                    + ((lane >> 3) & 1) * 16 + ks * 32;
                #pragma unroll
                for (int v = 0; v < 4; v++) ldm_x4(Kf[v], ka + v * VAR_KV);
                #pragma unroll
                for (int sub = 0; sub < 2; sub++) {
                    const int nt = np * 2 + sub;
                    const uint32_t* Krh = &Kf[0][sub * 2];
                    const uint32_t* Krl = &Kf[1][sub * 2];
                    const uint32_t* Kih = &Kf[2][sub * 2];
                    const uint32_t* Kil = &Kf[3][sub * 2];
                    mma16816(sR[nt], Qf[0], Krh);
                    mma16816(sR[nt], Qf[0], Krl);
                    mma16816(sR[nt], Qf[1], Krh);
                    mma16816(sR[nt], Qf[2], Kih);
                    mma16816(sR[nt], Qf[2], Kil);
                    mma16816(sR[nt], Qf[3], Kih);
                    mma16816(sI[nt], Qf[2], Krh);
                    mma16816(sI[nt], Qf[2], Krl);
                    mma16816(sI[nt], Qf[3], Krh);
                    mma16816(sI[nt], nQrh,  Kih);
                    mma16816(sI[nt], nQrh,  Kil);
                    mma16816(sI[nt], nQrl,  Kih);
                }
            }
        }

        float vm0 = -1e30f, vm1 = -1e30f;
        #pragma unroll
        for (int nt = 0; nt < 8; nt++)
            #pragma unroll
            for (int p = 0; p < 4; p++) {
                const float v = 0.125f * sqrtf(sR[nt][p] * sR[nt][p] + sI[nt][p] * sI[nt][p]);
                sR[nt][p] = v;
                if (p < 2) vm0 = fmaxf(vm0, v); else vm1 = fmaxf(vm1, v);
            }
        vm0 = fmaxf(vm0, __shfl_xor_sync(0xffffffffu, vm0, 1));
        vm0 = fmaxf(vm0, __shfl_xor_sync(0xffffffffu, vm0, 2));
        vm1 = fmaxf(vm1, __shfl_xor_sync(0xffffffffu, vm1, 1));
        vm1 = fmaxf(vm1, __shfl_xor_sync(0xffffffffu, vm1, 2));
        const float mn0 = fmaxf(m0, vm0), mn1 = fmaxf(m1, vm1);
        const float a0 = __expf(m0 - mn0), a1 = __expf(m1 - mn1);
        m0 = mn0; m1 = mn1;
        #pragma unroll
        for (int nt = 0; nt < 8; nt++)
            #pragma unroll
            for (int p = 0; p < 4; p++) {
                const float al = (p < 2) ? a0 : a1;
                oR[nt][p] *= al;
                oI[nt][p] *= al;
            }
        float s0 = 0.f, s1 = 0.f;
        #pragma unroll
        for (int nt = 0; nt < 8; nt++)
            #pragma unroll
            for (int p = 0; p < 4; p++) {
                const float pv = __expf(sR[nt][p] - ((p < 2) ? mn0 : mn1));
                sR[nt][p] = pv;
                if (p < 2) s0 += pv; else s1 += pv;
            }
        s0 += __shfl_xor_sync(0xffffffffu, s0, 1);
        s0 += __shfl_xor_sync(0xffffffffu, s0, 2);
        s1 += __shfl_xor_sync(0xffffffffu, s1, 1);
        s1 += __shfl_xor_sync(0xffffffffu, s1, 2);
        l0 = l0 * a0 + s0;
        l1 = l1 * a1 + s1;

        uint32_t Ph[4][4], Pl[4][4];
        #pragma unroll
        for (int j = 0; j < 4; j++) {
            const int t0 = 2 * j, t1 = 2 * j + 1;
            split2(sR[t0][0], sR[t0][1], Ph[j][0], Pl[j][0]);
            split2(sR[t0][2], sR[t0][3], Ph[j][1], Pl[j][1]);
            split2(sR[t1][0], sR[t1][1], Ph[j][2], Pl[j][2]);
            split2(sR[t1][2], sR[t1][3], Ph[j][3], Pl[j][3]);
        }

        #pragma unroll
        for (int j = 0; j < 4; j++) {
            #pragma unroll
            for (int g = 0; g < 4; g++) {
                uint32_t Vf[4][4];
                const uint32_t va = sV + (j * 16 + ((lane >> 3) & 1) * 8 + (lane & 7)) * PCH
                                    + (lane >> 4) * 16 + g * 32;
                #pragma unroll
                for (int v = 0; v < 4; v++) ldm_x4_t(Vf[v], va + v * VAR_KV);
                #pragma unroll
                for (int sub = 0; sub < 2; sub++) {
                    const int nt = g * 2 + sub;
                    const uint32_t* Vrh = &Vf[0][sub * 2];
                    const uint32_t* Vrl = &Vf[1][sub * 2];
                    const uint32_t* Vih = &Vf[2][sub * 2];
                    const uint32_t* Vil = &Vf[3][sub * 2];
                    mma16816(oR[nt], Ph[j], Vrh);
                    mma16816(oR[nt], Pl[j], Vrh);
                    mma16816(oR[nt], Ph[j], Vrl);
                    mma16816(oI[nt], Ph[j], Vih);
                    mma16816(oI[nt], Pl[j], Vih);
                    mma16816(oI[nt], Ph[j], Vil);
                }
            }
        }
        __syncthreads();
    }

    const float inv0 = 1.0f / l0, inv1 = 1.0f / l1;
    const int b = bh / HEADS, h = bh % HEADS;
    #pragma unroll
    for (int nt = 0; nt < 8; nt++)
        #pragma unroll
        for (int p = 0; p < 4; p++) {
            const int n = q0 + r0 + (lane >> 2) + (p >> 1) * 8;
            const int d = nt * 8 + (lane & 3) * 2 + (p & 1);
            const float inv = (p < 2) ? inv0 : inv1;
            const size_t idx = ((size_t)(b * Nn + n)) * DIMM + h * HD + d;
            wsplit(g_Ar_h, g_Ar_l, idx, oR[nt][p] * inv);
            wsplit(g_Ai_h, g_Ai_l, idx, oI[nt][p] * inv);
        }
}

// ---------------- launch ------------------------------------------------------
extern "C" void kernel_launch(void* const* d_in, const int* in_sizes, int n_in,
                              void* d_out, int out_size)
{
    const float* xr  = (const float*)d_in[0];
    const float* xi  = (const float*)d_in[1];
    const float* fr  = (const float*)d_in[2];
    const float* fi  = (const float*)d_in[3];
    const float* wqr = (const float*)d_in[4];
    const float* wqi = (const float*)d_in[5];
    const float* bqr = (const float*)d_in[6];
    const float* bqi = (const float*)d_in[7];
    const float* wor = (const float*)d_in[8];
    const float* woi = (const float*)d_in[9];
    const float* bor = (const float*)d_in[10];
    const float* boi = (const float*)d_in[11];
    float* out = (float*)d_out;

    cudaFuncSetAttribute(qkv_mma_kernel,
                         cudaFuncAttributeMaxDynamicSharedMemorySize, GEMM_SMEM);
    cudaFuncSetAttribute(out_mma_kernel,
                         cudaFuncAttributeMaxDynamicSharedMemorySize, GEMM_SMEM);
    cudaFuncSetAttribute(attn_mma_kernel,
                         cudaFuncAttributeMaxDynamicSharedMemorySize, ATTN_SMEM);

    split_all_kernel<<<12288, 256>>>(xr, xi, wqr, wqi, wor, woi);
    qkv_mma_kernel<<<dim3(E3 / 128, Mtot / 128), 256, GEMM_SMEM>>>(bqr, bqi, fr, fi);
    attn_mma_kernel<<<dim3(Nn / 128, Bb * HEADS), 256, ATTN_SMEM>>>();
    out_mma_kernel<<<dim3(DIMM / 128, Mtot / 128), 256, GEMM_SMEM>>>(bor, boi, out);
}